// round 8
// baseline (speedup 1.0000x reference)
#include <cuda_runtime.h>
#include <cstdint>
#include <math.h>

// Problem constants
constexpr int NN    = 4096;          // number of vertices / matrix dim
constexpr int TPB   = 1024;          // threads per MST block
constexpr int SLICE = NN / TPB;      // 4 vertices per thread
constexpr int NWARP = TPB / 32;      // 32 warps

// Scratch (no allocations allowed): final Prim parent arrays for both matrices.
__device__ int g_parent[2][NN];

__device__ __forceinline__ unsigned long long u64min(unsigned long long a, unsigned long long b) {
    return b < a ? b : a;
}

// ---------------------------------------------------------------------------
// Exact Prim's MST, one persistent CTA per matrix (gridDim.x == 2).
//
// Thread t owns vertices [4t, 4t+4).
//   md[k] : best edge weight from tree to vertex 4t+k. Sign bit set <=> vertex
//           is in the tree: strict `rv < md` always fails vs negative md, and
//           its u32 bit pattern (>= 0x80000000) loses every unsigned min vs
//           any live (nonnegative-float) candidate.
//   par[k]: tree endpoint realizing md (frozen once the vertex pops).
//
// Argmin matches jnp.argmin (first index) exactly:
//   - thread-local: u64 key (float_bits<<32 | idx), min keeps lowest idx on ties
//   - warp level:   REDUX.MIN on float bits; lane order == vertex order, so the
//                   FIRST lane whose bits equal the min holds the lowest index
//   - cross-warp:   warp id order == vertex-range order; same ballot/ffs trick
//
// Latency hiding (R7): the global winner is ALWAYS some warp's local winner.
// Each warp knows its local winner at the warp phase, ~150-200ns before the
// global j is known (STS + BAR + cross-warp phase). So every warp prefetches
// its own winner's full row into L2 right after its REDUX — the true next row
// is guaranteed to be in flight early, and since warp winners persist across
// iterations, the global runner-up's row (next winner ~25% of the time) was
// prefetched a full iteration earlier -> genuine L2 hit. Pure cache hints:
// the pop sequence is bit-identical.
//
// R6 lesson: at TPB=1024 the RF caps at 64 regs/thread; NO persistent
// speculative state in registers (it spilled). All additions here are scoped.
// ---------------------------------------------------------------------------
__global__ __launch_bounds__(TPB, 1)
void mst_kernel(const float* __restrict__ d1, const float* __restrict__ d2) {
    const float* __restrict__ D = blockIdx.x ? d2 : d1;
    const int t    = threadIdx.x;
    const int wid  = t >> 5;
    const int lane = t & 31;
    constexpr unsigned FULL = 0xFFFFFFFFu;

    // per-warp winner (bits, idx), double-buffered across iterations
    __shared__ unsigned pb[2][NWARP];
    __shared__ unsigned pi[2][NWARP];

    float md[SLICE];
    int   par[SLICE];

    // ---- init: min_dist = D[0, :], parent = 0, vertex 0 in tree ----
    {
        float4 a = reinterpret_cast<const float4*>(D)[t];
        md[0] = a.x; md[1] = a.y; md[2] = a.z; md[3] = a.w;
    }
#pragma unroll
    for (int k = 0; k < SLICE; ++k) par[k] = 0;
    if (t == 0) md[0] = __uint_as_float(0xFF800000u);   // vertex 0: -inf => in tree

    // thread-local argmin key over owned slice
    unsigned long long key = ~0ull;
#pragma unroll
    for (int k = 0; k < SLICE; ++k) {
        unsigned long long kk =
            ((unsigned long long)__float_as_uint(md[k]) << 32) | (unsigned)(t * SLICE + k);
        key = u64min(key, kk);
    }

    for (int sel = 0; sel < NN - 1; ++sel) {
        const int s = sel & 1;
        const unsigned bits = (unsigned)(key >> 32);
        const unsigned idx  = (unsigned)key;

        // ---- warp phase: single-instruction min + first-matching-lane store ----
        const unsigned wmin  = __reduce_min_sync(FULL, bits);
        const unsigned ball  = __ballot_sync(FULL, bits == wmin);
        const int      wsrc  = __ffs((int)ball) - 1;   // first lane == lowest vertex idx on ties
        if (lane == wsrc) {
            pb[s][wid] = bits;
            pi[s][wid] = idx;
        }

        // ---- per-warp winner prefetch: the next global row is ALWAYS one of
        //      these 32 rows; issue 128 L2-line hints (4 per lane) now, giving
        //      the real load a ~150-200ns head start. Repeats hit L2 (cheap).
        {
            const unsigned widx = __shfl_sync(FULL, idx, wsrc);
            if (wmin < 0x80000000u) {    // warp not fully in-tree
                const char* p = reinterpret_cast<const char*>(D + (size_t)widx * NN) + lane * 128;
#pragma unroll
                for (int k = 0; k < 4; ++k)
                    asm volatile("prefetch.global.L2 [%0];" :: "l"(p + k * 4096));
            }
        }
        __syncthreads();

        // ---- cross-warp phase: 32 partials, one per lane ----
        const unsigned b2 = pb[s][lane];
        const unsigned i2 = pi[s][lane];
        const unsigned gmin  = __reduce_min_sync(FULL, b2);
        const unsigned ball2 = __ballot_sync(FULL, b2 == gmin);
        const int src = __ffs((int)ball2) - 1;            // lowest warp id with min
        const int j   = (int)__shfl_sync(FULL, i2, src);  // broadcast winner index

        // owner marks j in-tree (sign-bit flip), static register indexing only
        if ((j >> 2) == t) {
#pragma unroll
            for (int k = 0; k < SLICE; ++k)
                if (k == (j & (SLICE - 1)))
                    md[k] = __uint_as_float(__float_as_uint(md[k]) | 0x80000000u);
        }
        if (sel == NN - 2) break;   // last vertex popped, no relaxation needed

        // ---- row-j load (merges with the in-flight L2 prefetch of row j) ----
        float4 a = reinterpret_cast<const float4*>(D + (size_t)j * NN)[t];

        // ---- relax with row j, fused with local argmin recompute ----
        float rv[SLICE] = {a.x, a.y, a.z, a.w};
        key = ~0ull;
#pragma unroll
        for (int k = 0; k < SLICE; ++k) {
            if (rv[k] < md[k]) { md[k] = rv[k]; par[k] = j; }   // strict <, matches reference
            unsigned long long kk =
                ((unsigned long long)__float_as_uint(md[k]) << 32) | (unsigned)(t * SLICE + k);
            key = u64min(key, kk);
        }
    }

    // parents are frozen at pop time; write once at the end
#pragma unroll
    for (int k = 0; k < SLICE; ++k)
        g_parent[blockIdx.x][t * SLICE + k] = par[k];
}

// ---------------------------------------------------------------------------
// Gather signatures, fp64 sums, sqrt, matched-pair count.
// Each child c in 1..N-1 appears exactly once in each pair list, so
// matched_pairs = #{ c : parent1[c] == parent2[c] }.
// ---------------------------------------------------------------------------
__global__ __launch_bounds__(1024)
void finalize_kernel(const float* __restrict__ d1, const float* __restrict__ d2,
                     float* __restrict__ out, int out_size) {
    constexpr int FT = 1024;
    __shared__ double s12[FT];
    __shared__ double s21[FT];
    __shared__ int    sm[FT];
    const int t = threadIdx.x;

    double a12 = 0.0, a21 = 0.0;
    int m = 0;
#pragma unroll
    for (int i = 0; i < 4; ++i) {
        int c = 1 + t + i * FT;
        if (c < NN) {
            int p1 = g_parent[0][c];
            int p2 = g_parent[1][c];
            float x1 = d1[(size_t)p1 * NN + c];   // sig1
            float y1 = d2[(size_t)p1 * NN + c];   // sig1_2
            float x2 = d2[(size_t)p2 * NN + c];   // sig2
            float y2 = d1[(size_t)p2 * NN + c];   // sig2_1
            double e1 = (double)x1 - (double)y1;
            double e2 = (double)x2 - (double)y2;
            a12 += e1 * e1;
            a21 += e2 * e2;
            m += (p1 == p2);
        }
    }
    s12[t] = a12; s21[t] = a21; sm[t] = m;
    __syncthreads();
#pragma unroll
    for (int o = FT / 2; o; o >>= 1) {
        if (t < o) {
            s12[t] += s12[t + o];
            s21[t] += s21[t + o];
            sm[t]  += sm[t + o];
        }
        __syncthreads();
    }
    if (t == 0) {
        double D12 = sqrt(s12[0]);
        double D21 = sqrt(s21[0]);
        if (out_size > 0) out[0] = (float)(D12 + D21);   // distance
        if (out_size > 1) out[1] = (float)D12;           // distance1_2
        if (out_size > 2) out[2] = (float)D21;           // distance2_1
        if (out_size > 3) out[3] = (float)sm[0];         // matched_pairs
    }
}

extern "C" void kernel_launch(void* const* d_in, const int* in_sizes, int n_in,
                              void* d_out, int out_size) {
    const float* d1 = (const float*)d_in[0];   // distances1 [4096,4096] f32
    const float* d2 = (const float*)d_in[1];   // distances2 [4096,4096] f32
    float* out = (float*)d_out;

    // Two persistent CTAs, one exact Prim's MST each (runs concurrently).
    mst_kernel<<<2, TPB>>>(d1, d2);
    // Tiny epilogue: gathers + fp64 reductions + matched-pair count.
    finalize_kernel<<<1, 1024>>>(d1, d2, out, out_size);
}

// round 9
// speedup vs baseline: 3.8685x; 3.8685x over previous
#include <cuda_runtime.h>
#include <cstdint>
#include <math.h>

// Problem constants
constexpr int NN    = 4096;          // number of vertices / matrix dim
constexpr int TPB   = 1024;          // threads per MST block
constexpr int SLICE = NN / TPB;      // 4 vertices per thread
constexpr int NWARP = TPB / 32;      // 32 warps

// Scratch (no allocations allowed): final Prim parent arrays for both matrices.
__device__ int g_parent[2][NN];

__device__ __forceinline__ unsigned long long u64min(unsigned long long a, unsigned long long b) {
    return b < a ? b : a;
}

// ---------------------------------------------------------------------------
// Exact Prim's MST, one persistent CTA per matrix (gridDim.x == 2).
//
// Thread t owns vertices [4t, 4t+4).
//   md[k] : best edge weight from tree to vertex 4t+k. Sign bit set <=> vertex
//           is in the tree: strict `rv < md` always fails vs negative md, and
//           its u32 bit pattern (>= 0x80000000) loses every unsigned min vs
//           any live (nonnegative-float) candidate.
//   par[k]: tree endpoint realizing md (frozen once the vertex pops).
//
// Argmin matches jnp.argmin (first index) exactly:
//   - thread-local: u64 key (float_bits<<32 | idx), min keeps lowest idx on ties
//   - warp level:   REDUX.MIN on float bits; lane order == vertex order, so the
//                   FIRST lane whose bits equal the min holds the lowest index
//   - cross-warp:   warp id order == vertex-range order; same ballot/ffs trick
//
// Latency hiding (R8): the winner of iteration s+1 is the runner-up j2 of
// iteration s unless the fresh row-j relaxation creates a new minimum. Each
// iteration issues cp.async (LDGSTS) of row j2 into a double-buffered smem
// region (1024 threads x 16B = one 16KB row = 128 cache lines — R5-proven
// safe footprint; R7's 4096-line flood is the documented disaster). On a hit
// the row is read from smem (~29cyc) instead of DRAM; on a miss the normal
// global load is issued and the .cg fill still leaves the row in L2 for later.
// No registers are held across iterations (R6 spill lesson); no mass
// prefetch (R7 queue lesson). Pure data movement — pop sequence bit-exact.
// ---------------------------------------------------------------------------
__global__ __launch_bounds__(TPB, 1)
void mst_kernel(const float* __restrict__ d1, const float* __restrict__ d2) {
    const float* __restrict__ D = blockIdx.x ? d2 : d1;
    const int t    = threadIdx.x;
    const int wid  = t >> 5;
    const int lane = t & 31;
    constexpr unsigned FULL = 0xFFFFFFFFu;

    // per-warp winner (bits, idx), double-buffered across iterations
    __shared__ unsigned pb[2][NWARP];
    __shared__ unsigned pi[2][NWARP];
    // speculative next-row buffers (double-buffered, 16KB each)
    __shared__ __align__(16) float specbuf[2][NN];

    float md[SLICE];
    int   par[SLICE];

    // ---- init: min_dist = D[0, :], parent = 0, vertex 0 in tree ----
    {
        float4 a = reinterpret_cast<const float4*>(D)[t];
        md[0] = a.x; md[1] = a.y; md[2] = a.z; md[3] = a.w;
    }
#pragma unroll
    for (int k = 0; k < SLICE; ++k) par[k] = 0;
    if (t == 0) md[0] = __uint_as_float(0xFF800000u);   // vertex 0: -inf => in tree

    // thread-local argmin key over owned slice
    unsigned long long key = ~0ull;
#pragma unroll
    for (int k = 0; k < SLICE; ++k) {
        unsigned long long kk =
            ((unsigned long long)__float_as_uint(md[k]) << 32) | (unsigned)(t * SLICE + k);
        key = u64min(key, kk);
    }

    int spec_idx = -1;   // row currently (being) staged in specbuf[(sel-1)&1]

    for (int sel = 0; sel < NN - 1; ++sel) {
        const int s = sel & 1;
        const unsigned bits = (unsigned)(key >> 32);
        const unsigned idx  = (unsigned)key;

        // ---- warp phase: single-instruction min + first-matching-lane store ----
        const unsigned wmin = __reduce_min_sync(FULL, bits);
        const unsigned ball = __ballot_sync(FULL, bits == wmin);
        const int      wsrc = __ffs((int)ball) - 1;   // first lane == lowest vertex idx on ties
        if (lane == wsrc) {
            pb[s][wid] = bits;
            pi[s][wid] = idx;
        }
        __syncthreads();

        // ---- cross-warp phase: 32 partials, one per lane ----
        const unsigned b2 = pb[s][lane];
        const unsigned i2 = pi[s][lane];
        const unsigned gmin  = __reduce_min_sync(FULL, b2);
        const unsigned ball2 = __ballot_sync(FULL, b2 == gmin);
        const int src = __ffs((int)ball2) - 1;            // lowest warp id with min
        const int j   = (int)__shfl_sync(FULL, i2, src);  // broadcast winner index

        // owner marks j in-tree (sign-bit flip), static register indexing only
        if ((j >> 2) == t) {
#pragma unroll
            for (int k = 0; k < SLICE; ++k)
                if (k == (j & (SLICE - 1)))
                    md[k] = __uint_as_float(__float_as_uint(md[k]) | 0x80000000u);
        }
        if (sel == NN - 2) break;   // last vertex popped, no relaxation needed

        // ---- row-j data: speculation hit => staged in smem (block-uniform) ----
        float4 a;
        if (j == spec_idx) {
            // this thread staged its own 16B slice; thread-local wait suffices
            asm volatile("cp.async.wait_all;" ::: "memory");
            a = reinterpret_cast<const float4*>(&specbuf[s ^ 1][0])[t];  // written at sel-1
        } else {
            a = reinterpret_cast<const float4*>(D + (size_t)j * NN)[t];  // issue now
        }

        // ---- runner-up j2 (next-winner prediction): stage its row via cp.async.
        //      Chain + LDGSTS hide under the in-flight row load on misses. ----
        {
            const unsigned b2x   = (lane == src) ? 0xFFFFFFFFu : b2;
            const unsigned gmin2 = __reduce_min_sync(FULL, b2x);
            const unsigned ball3 = __ballot_sync(FULL, b2x == gmin2);
            const int src2 = __ffs((int)ball3) - 1;
            const int j2   = (int)__shfl_sync(FULL, i2, src2);
            spec_idx = j2;
            const float* gsrc = D + (size_t)j2 * NN + t * 4;
            const unsigned dsts =
                (unsigned)__cvta_generic_to_shared(&specbuf[s][0]) + (unsigned)(t * 16);
            asm volatile("cp.async.cg.shared.global [%0], [%1], 16;\n"
                         "cp.async.commit_group;\n" :: "r"(dsts), "l"(gsrc) : "memory");
        }

        // ---- relax with row j, fused with local argmin recompute ----
        float rv[SLICE] = {a.x, a.y, a.z, a.w};
        key = ~0ull;
#pragma unroll
        for (int k = 0; k < SLICE; ++k) {
            if (rv[k] < md[k]) { md[k] = rv[k]; par[k] = j; }   // strict <, matches reference
            unsigned long long kk =
                ((unsigned long long)__float_as_uint(md[k]) << 32) | (unsigned)(t * SLICE + k);
            key = u64min(key, kk);
        }
    }

    // drain any outstanding speculative copies before smem goes away
    asm volatile("cp.async.wait_all;" ::: "memory");

    // parents are frozen at pop time; write once at the end
#pragma unroll
    for (int k = 0; k < SLICE; ++k)
        g_parent[blockIdx.x][t * SLICE + k] = par[k];
}

// ---------------------------------------------------------------------------
// Gather signatures, fp64 sums, sqrt, matched-pair count.
// Each child c in 1..N-1 appears exactly once in each pair list, so
// matched_pairs = #{ c : parent1[c] == parent2[c] }.
// ---------------------------------------------------------------------------
__global__ __launch_bounds__(1024)
void finalize_kernel(const float* __restrict__ d1, const float* __restrict__ d2,
                     float* __restrict__ out, int out_size) {
    constexpr int FT = 1024;
    __shared__ double s12[FT];
    __shared__ double s21[FT];
    __shared__ int    sm[FT];
    const int t = threadIdx.x;

    double a12 = 0.0, a21 = 0.0;
    int m = 0;
#pragma unroll
    for (int i = 0; i < 4; ++i) {
        int c = 1 + t + i * FT;
        if (c < NN) {
            int p1 = g_parent[0][c];
            int p2 = g_parent[1][c];
            float x1 = d1[(size_t)p1 * NN + c];   // sig1
            float y1 = d2[(size_t)p1 * NN + c];   // sig1_2
            float x2 = d2[(size_t)p2 * NN + c];   // sig2
            float y2 = d1[(size_t)p2 * NN + c];   // sig2_1
            double e1 = (double)x1 - (double)y1;
            double e2 = (double)x2 - (double)y2;
            a12 += e1 * e1;
            a21 += e2 * e2;
            m += (p1 == p2);
        }
    }
    s12[t] = a12; s21[t] = a21; sm[t] = m;
    __syncthreads();
#pragma unroll
    for (int o = FT / 2; o; o >>= 1) {
        if (t < o) {
            s12[t] += s12[t + o];
            s21[t] += s21[t + o];
            sm[t]  += sm[t + o];
        }
        __syncthreads();
    }
    if (t == 0) {
        double D12 = sqrt(s12[0]);
        double D21 = sqrt(s21[0]);
        if (out_size > 0) out[0] = (float)(D12 + D21);   // distance
        if (out_size > 1) out[1] = (float)D12;           // distance1_2
        if (out_size > 2) out[2] = (float)D21;           // distance2_1
        if (out_size > 3) out[3] = (float)sm[0];         // matched_pairs
    }
}

extern "C" void kernel_launch(void* const* d_in, const int* in_sizes, int n_in,
                              void* d_out, int out_size) {
    const float* d1 = (const float*)d_in[0];   // distances1 [4096,4096] f32
    const float* d2 = (const float*)d_in[1];   // distances2 [4096,4096] f32
    float* out = (float*)d_out;

    // Two persistent CTAs, one exact Prim's MST each (runs concurrently).
    mst_kernel<<<2, TPB>>>(d1, d2);
    // Tiny epilogue: gathers + fp64 reductions + matched-pair count.
    finalize_kernel<<<1, 1024>>>(d1, d2, out, out_size);
}